// round 12
// baseline (speedup 1.0000x reference)
#include <cuda_runtime.h>
#include <cuda_bf16.h>

// Problem constants
#define BATCH     8192
#define NUM_CODES 16
#define BOOK_SIZE 1024
#define EMBED_DIM 64

// Tiling
#define MB     128   // x rows per CTA
#define CHUNK  64    // codebook rows per smem tile
#define CSTR   9     // uint4 stride per code in csf (9 -> conflict-free reads)

#define NPAIR (BATCH * NUM_CODES)
#define CW_ELEMS ((size_t)BATCH * NUM_CODES * EMBED_DIM)   // 8,388,608

// Near-tie band on EXACT distance gap (proven in R5 pass — do not change)
#define TIE_EPS 4e-5
// refine gate: bf16 input noise (5 sigma ~ 0.22) + key truncation (0.0625)
#define MARGIN  0.5f
// bias making scores positive so uint order == float order
#define C2BIAS  512.0f

// Scratch (device globals; no allocation allowed)
__device__ float g_c2[NUM_CODES * BOOK_SIZE];   // stores c2 + C2BIAS

// ---------------------------------------------------------------------------
// pack two fp32 into bf16x2: low half = lo, high half = hi
__device__ __forceinline__ unsigned int pbf16(float lo, float hi) {
    unsigned int r;
    asm("cvt.rn.bf16x2.f32 %0, %1, %2;" : "=r"(r) : "f"(hi), "f"(lo));
    return r;
}
__device__ __forceinline__ void mma_bf16(float& d0, float& d1, float& d2, float& d3,
                                         unsigned int a0, unsigned int a1,
                                         unsigned int a2, unsigned int a3,
                                         unsigned int b0, unsigned int b1) {
    asm("mma.sync.aligned.m16n8k16.row.col.f32.bf16.bf16.f32 "
        "{%0,%1,%2,%3}, {%4,%5,%6,%7}, {%8,%9}, {%0,%1,%2,%3};"
        : "+f"(d0), "+f"(d1), "+f"(d2), "+f"(d3)
        : "r"(a0), "r"(a1), "r"(a2), "r"(a3), "r"(b0), "r"(b1));
}

// top-3 (ascending) insertion of key k into sorted triple: 5 integer min/max
__device__ __forceinline__ void ins3(unsigned int& k0, unsigned int& k1,
                                     unsigned int& k2, unsigned int k) {
    unsigned int a = umin(k, k0);
    unsigned int b = umax(k, k0);
    unsigned int c = umin(b, k1);
    unsigned int d = umax(b, k1);
    k2 = umin(d, k2);
    k1 = c;
    k0 = a;
}

__device__ __forceinline__ float debias(unsigned int key) {
    return __uint_as_float(key & 0xFFFFFC00u) - C2BIAS;
}

// ---------------------------------------------------------------------------
// Kernel 0: codebook squared norms + bias.
// ---------------------------------------------------------------------------
__global__ void c2_kernel(const float* __restrict__ cb) {
    int code = blockIdx.x * blockDim.x + threadIdx.x;
    if (code < NUM_CODES * BOOK_SIZE) {
        const float4* p = (const float4*)(cb + (size_t)code * EMBED_DIM);
        float s = 0.f;
        #pragma unroll
        for (int i = 0; i < EMBED_DIM / 4; i++) {
            float4 v = p[i];
            s += v.x * v.x + v.y * v.y + v.z * v.z + v.w * v.w;
        }
        g_c2[code] = s + C2BIAS;
    }
}

// ---------------------------------------------------------------------------
// Kernel 1 (fused): bf16 tensor ranking + one-hot zero-fill + in-warp refine
// + output write. 128 threads = 4 warps; warp w owns rows [w*32, w*32+32) as
// two m16 A-sets. Keys: (bits of (c2 + 512 - 2*dot) & ~0x3FF) | code.
// Each pair's 12 candidates end up in one quad (lanes 4g..4g+3, 3 keys each,
// disjoint code sets per lane) -> refine + finalize are quad-local.
// ---------------------------------------------------------------------------
__global__ void __launch_bounds__(128)
argmin_kernel(const float* __restrict__ x, const float* __restrict__ cb,
              float* __restrict__ out) {
    __shared__ float xs[EMBED_DIM][MB];        // 32 KB, transposed x tile
    __shared__ uint4 csf[CHUNK * CSTR];        // 9 KB, bf16 B fragments

    const int tid  = threadIdx.x;
    const int w    = tid >> 5;
    const int lane = tid & 31;
    const int g    = lane >> 2;
    const int t    = lane & 3;
    const int n    = blockIdx.y;
    const int row0 = blockIdx.x * MB;
    const int rw   = w * 32;   // warp's row base within tile (32 rows)

    const float* xbase = x  + (size_t)row0 * (NUM_CODES * EMBED_DIM) + n * EMBED_DIM;
    const float* cbase = cb + (size_t)n * (BOOK_SIZE * EMBED_DIM);
    const float* c2b   = &g_c2[n * BOOK_SIZE];
    float4* ohz = (float4*)(out + CW_ELEMS + ((size_t)row0 * NUM_CODES + n) * BOOK_SIZE);
    const float4 zero4 = make_float4(0.f, 0.f, 0.f, 0.f);

    // Load x tile (transposed). 128 rows x 16 float4 columns, coalesced.
    for (int it = tid; it < MB * (EMBED_DIM / 4); it += 128) {
        int r  = it >> 4;
        int c4 = it & 15;
        float4 v = *(const float4*)(xbase + (size_t)r * (NUM_CODES * EMBED_DIM) + c4 * 4);
        xs[c4 * 4 + 0][r] = v.x;
        xs[c4 * 4 + 1][r] = v.y;
        xs[c4 * 4 + 2][r] = v.z;
        xs[c4 * 4 + 3][r] = v.w;
    }
    __syncthreads();

    // A fragments (bf16x2), two m16 row-sets, K=64 = 4 k16-steps.
    unsigned int a[2][4][4];
    #pragma unroll
    for (int m = 0; m < 2; m++) {
        const int rb = rw + m * 16;
        #pragma unroll
        for (int s = 0; s < 4; s++) {
            int k0 = 16 * s + 2 * t;
            a[m][s][0] = pbf16(xs[k0    ][rb + g    ], xs[k0 + 1][rb + g    ]);
            a[m][s][1] = pbf16(xs[k0    ][rb + g + 8], xs[k0 + 1][rb + g + 8]);
            a[m][s][2] = pbf16(xs[k0 + 8][rb + g    ], xs[k0 + 9][rb + g    ]);
            a[m][s][3] = pbf16(xs[k0 + 8][rb + g + 8], xs[k0 + 9][rb + g + 8]);
        }
    }

    // Per-thread top-3 packed keys for each of the 4 rows this thread owns.
    unsigned int kk[4][3];
    #pragma unroll
    for (int h = 0; h < 4; h++)
        #pragma unroll
        for (int j = 0; j < 3; j++) kk[h][j] = 0xFFFFFFFFu;

    unsigned int* csf32 = (unsigned int*)csf;
    int it2 = 0;   // zero-fill progress counter (2 float4 per tile iter)

    for (int c0 = 0; c0 < BOOK_SIZE; c0 += CHUNK) {
        __syncthreads();
        // Fill csf: CHUNK codes x 16 float4 columns, pack to bf16x2 once.
        for (int it = tid; it < CHUNK * (EMBED_DIM / 4); it += 128) {
            int code = it >> 4;
            int c4   = it & 15;
            int s    = c4 >> 2;
            int p0   = (c4 & 3) * 2;
            float4 v = *(const float4*)(cbase + (size_t)(c0 + code) * EMBED_DIM + c4 * 4);
            unsigned int w0 = pbf16(v.x, v.y);
            unsigned int w1 = pbf16(v.z, v.w);
            int half = s >> 1, rem = (s & 1) * 2;
            int t0 = p0 & 3,        b0 = p0 >> 2;
            int t1 = (p0 + 1) & 3,  b1 = (p0 + 1) >> 2;
            csf32[(code * CSTR + t0 * 2 + half) * 4 + rem + b0] = w0;
            csf32[(code * CSTR + t1 * 2 + half) * 4 + rem + b1] = w1;
        }
        __syncthreads();

        #pragma unroll
        for (int tc = 0; tc < CHUNK / 8; tc++) {
            const int cbs = tc * 8;
            const int cg  = c0 + cbs;
            const int code = cbs + g;

            // background one-hot zero-fill: 2 coalesced float4 per thread
            {
                int j0 = it2 * 2;
                int L0 = j0 * 128 + tid;          // row = L>>8, f4 = L&255
                int L1 = L0 + 128;
                __stwt(&ohz[((size_t)(L0 >> 8)) * (NUM_CODES * 256) + (L0 & 255)], zero4);
                __stwt(&ohz[((size_t)(L1 >> 8)) * (NUM_CODES * 256) + (L1 & 255)], zero4);
                it2++;
            }

            // 2 LDS.128: full K=64 B fragment for this thread's code.
            uint4 U0 = csf[code * CSTR + t * 2    ];
            uint4 U1 = csf[code * CSTR + t * 2 + 1];

            float2 c2v = *(const float2*)(c2b + cg + 2 * t);   // biased c2
            unsigned int code0 = cg + 2 * t, code1 = code0 + 1;

            #pragma unroll
            for (int m = 0; m < 2; m++) {
                float d0 = 0.f, d1 = 0.f, d2 = 0.f, d3 = 0.f;
                mma_bf16(d0, d1, d2, d3, a[m][0][0], a[m][0][1], a[m][0][2], a[m][0][3], U0.x, U0.y);
                mma_bf16(d0, d1, d2, d3, a[m][1][0], a[m][1][1], a[m][1][2], a[m][1][3], U0.z, U0.w);
                mma_bf16(d0, d1, d2, d3, a[m][2][0], a[m][2][1], a[m][2][2], a[m][2][3], U1.x, U1.y);
                mma_bf16(d0, d1, d2, d3, a[m][3][0], a[m][3][1], a[m][3][2], a[m][3][3], U1.z, U1.w);

                unsigned int k;
                k = (__float_as_uint(fmaf(-2.0f, d0, c2v.x)) & 0xFFFFFC00u) | code0;
                ins3(kk[2*m][0], kk[2*m][1], kk[2*m][2], k);
                k = (__float_as_uint(fmaf(-2.0f, d1, c2v.y)) & 0xFFFFFC00u) | code1;
                ins3(kk[2*m][0], kk[2*m][1], kk[2*m][2], k);
                k = (__float_as_uint(fmaf(-2.0f, d2, c2v.x)) & 0xFFFFFC00u) | code0;
                ins3(kk[2*m+1][0], kk[2*m+1][1], kk[2*m+1][2], k);
                k = (__float_as_uint(fmaf(-2.0f, d3, c2v.y)) & 0xFFFFFC00u) | code1;
                ins3(kk[2*m+1][0], kk[2*m+1][1], kk[2*m+1][2], k);
            }
        }
    }

    // Order the zero-fill stores before the hot-element writes, and make xs
    // stable for the fp64 slow path.
    __syncthreads();

    const unsigned int qmask = 0xFu << (lane & ~3);

    #pragma unroll 1
    for (int h = 0; h < 4; h++) {
        const int rloc = rw + (h >> 1) * 16 + g + (h & 1) * 8;  // row in tile
        const int row  = row0 + rloc;
        const int bn   = row * NUM_CODES + n;

        // quad-min packed key (value, then lowest code on truncated ties)
        unsigned int kmin = kk[h][0];
        kmin = umin(kmin, __shfl_xor_sync(0xffffffffu, kmin, 1));
        kmin = umin(kmin, __shfl_xor_sync(0xffffffffu, kmin, 2));
        const float thr = debias(kmin) + MARGIN;

        int cnt = 0;
        #pragma unroll
        for (int j = 0; j < 3; j++) cnt += (debias(kk[h][j]) <= thr);
        cnt += __shfl_xor_sync(0xffffffffu, cnt, 1);
        cnt += __shfl_xor_sync(0xffffffffu, cnt, 2);

        int win = (int)(kmin & 0x3FFu);

        if (cnt > 1) {
            // Exact fp64 distances for all candidates within MARGIN; winner =
            // lowest code among those within TIE_EPS of the exact min.
            double dloc[3] = {1e300, 1e300, 1e300};
            #pragma unroll 1
            for (int tq = 0; tq < 4; tq++) {
                #pragma unroll 1
                for (int s = 0; s < 3; s++) {
                    unsigned int key = __shfl_sync(qmask, kk[h][s], (lane & ~3) + tq);
                    if (debias(key) <= thr) {   // quad-uniform branch
                        int code = (int)(key & 0x3FFu);
                        const float* cc = cbase + (size_t)code * EMBED_DIM;
                        double part = 0.0;
                        #pragma unroll
                        for (int u = 0; u < 16; u++) {
                            int k = (lane & 3) * 16 + u;
                            double cv = (double)cc[k];
                            double xv = (double)xs[k][rloc];
                            part += cv * cv - 2.0 * xv * cv;
                        }
                        part += __shfl_xor_sync(qmask, part, 1);
                        part += __shfl_xor_sync(qmask, part, 2);
                        if ((lane & 3) == tq) dloc[s] = part;
                    }
                }
            }
            double dmin = fmin(dloc[0], fmin(dloc[1], dloc[2]));
            dmin = fmin(dmin, __shfl_xor_sync(qmask, dmin, 1));
            dmin = fmin(dmin, __shfl_xor_sync(qmask, dmin, 2));
            int key = 0x7fffffff;
            #pragma unroll
            for (int s = 0; s < 3; s++)
                if (dloc[s] <= dmin + TIE_EPS)
                    key = min(key, (int)(kk[h][s] & 0x3FFu));
            key = min(key, __shfl_xor_sync(qmask, key, 1));
            key = min(key, __shfl_xor_sync(qmask, key, 2));
            win = key;
        }

        // outputs for this pair
        if ((lane & 3) == 0)
            out[CW_ELEMS + (size_t)bn * BOOK_SIZE + win] = 1.0f;

        const float4* src = (const float4*)(cbase + (size_t)win * EMBED_DIM);
        float4* dst = (float4*)(out + (size_t)row * (NUM_CODES * EMBED_DIM) + n * EMBED_DIM);
        #pragma unroll
        for (int u = 0; u < 4; u++) {
            int f4 = (lane & 3) + 4 * u;
            __stwt(&dst[f4], src[f4]);
        }
    }
}

// ---------------------------------------------------------------------------
extern "C" void kernel_launch(void* const* d_in, const int* in_sizes, int n_in,
                              void* d_out, int out_size) {
    const float* x  = (const float*)d_in[0];
    const float* cb = (const float*)d_in[1];
    if (n_in >= 2 && in_sizes[0] == NUM_CODES * BOOK_SIZE * EMBED_DIM) {
        const float* tmp = x; x = cb; cb = tmp;
    }
    float* out = (float*)d_out;

    c2_kernel<<<(NUM_CODES * BOOK_SIZE + 255) / 256, 256>>>(cb);

    dim3 g1(BATCH / MB, NUM_CODES);
    argmin_kernel<<<g1, 128>>>(x, cb, out);
}

// round 13
// speedup vs baseline: 1.6608x; 1.6608x over previous
#include <cuda_runtime.h>
#include <cuda_bf16.h>

// Problem constants
#define BATCH     8192
#define NUM_CODES 16
#define BOOK_SIZE 1024
#define EMBED_DIM 64

// Tiling
#define MB     128   // x rows per CTA
#define CHUNK  64    // codebook rows per smem tile
#define CSTR   9     // uint4 stride per code in csf (9 -> conflict-free reads)

#define NPAIR (BATCH * NUM_CODES)
#define CW_ELEMS ((size_t)BATCH * NUM_CODES * EMBED_DIM)   // 8,388,608

// Near-tie band on EXACT distance gap (proven in R5 pass — do not change)
#define TIE_EPS 4e-5
// refine gate: bf16 input noise (5 sigma ~ 0.22) + key truncation (0.0625)
#define MARGIN  0.5f
// bias making scores positive so uint order == float order
#define C2BIAS  512.0f

// Scratch (device globals; no allocation allowed)
__device__ float g_c2  [NUM_CODES * BOOK_SIZE];   // stores c2 + C2BIAS
__device__ int   g_cand[(size_t)NPAIR * 12];
__device__ float g_cval[(size_t)NPAIR * 12];
__device__ int   g_idx [NPAIR];

// ---------------------------------------------------------------------------
// pack two fp32 into bf16x2: low half = lo, high half = hi
__device__ __forceinline__ unsigned int pbf16(float lo, float hi) {
    unsigned int r;
    asm("cvt.rn.bf16x2.f32 %0, %1, %2;" : "=r"(r) : "f"(hi), "f"(lo));
    return r;
}
__device__ __forceinline__ void mma_bf16(float& d0, float& d1, float& d2, float& d3,
                                         unsigned int a0, unsigned int a1,
                                         unsigned int a2, unsigned int a3,
                                         unsigned int b0, unsigned int b1) {
    asm("mma.sync.aligned.m16n8k16.row.col.f32.bf16.bf16.f32 "
        "{%0,%1,%2,%3}, {%4,%5,%6,%7}, {%8,%9}, {%0,%1,%2,%3};"
        : "+f"(d0), "+f"(d1), "+f"(d2), "+f"(d3)
        : "r"(a0), "r"(a1), "r"(a2), "r"(a3), "r"(b0), "r"(b1));
}

// top-3 (ascending) insertion of key k into sorted triple: 5 integer min/max
__device__ __forceinline__ void ins3(unsigned int& k0, unsigned int& k1,
                                     unsigned int& k2, unsigned int k) {
    unsigned int a = umin(k, k0);
    unsigned int b = umax(k, k0);
    unsigned int c = umin(b, k1);
    unsigned int d = umax(b, k1);
    k2 = umin(d, k2);
    k1 = c;
    k0 = a;
}

// ---------------------------------------------------------------------------
// Kernel 0: codebook squared norms + bias.
// ---------------------------------------------------------------------------
__global__ void c2_kernel(const float* __restrict__ cb) {
    int code = blockIdx.x * blockDim.x + threadIdx.x;
    if (code < NUM_CODES * BOOK_SIZE) {
        const float4* p = (const float4*)(cb + (size_t)code * EMBED_DIM);
        float s = 0.f;
        #pragma unroll
        for (int i = 0; i < EMBED_DIM / 4; i++) {
            float4 v = p[i];
            s += v.x * v.x + v.y * v.y + v.z * v.z + v.w * v.w;
        }
        g_c2[code] = s + C2BIAS;
    }
}

// ---------------------------------------------------------------------------
// Kernel 1: bf16 tensor ranking + fused one-hot zero-fill.
// 256 threads = 8 warps; warp w owns rows [w*16, w*16+16) (one m16 A-set,
// 16 regs) -> low reg pressure, 4 CTAs/SM, ~50% occupancy.
// Keys: (bits of (c2 + 512 - 2*dot) & ~0x3FF) | code  (uint order = float
// order for positives; low-bit code -> ties resolve to lowest index).
// ---------------------------------------------------------------------------
__global__ void __launch_bounds__(256, 4)
argmin_kernel(const float* __restrict__ x, const float* __restrict__ cb,
              float* __restrict__ out) {
    __shared__ float xs[EMBED_DIM][MB];        // 32 KB, transposed x tile
    __shared__ uint4 csf[CHUNK * CSTR];        // 9 KB, bf16 B fragments

    const int tid  = threadIdx.x;
    const int w    = tid >> 5;
    const int lane = tid & 31;
    const int g    = lane >> 2;
    const int t    = lane & 3;
    const int n    = blockIdx.y;
    const int row0 = blockIdx.x * MB;
    const int rw   = w * 16;   // warp's row base within tile

    const float* xbase = x  + (size_t)row0 * (NUM_CODES * EMBED_DIM) + n * EMBED_DIM;
    const float* cbase = cb + (size_t)n * (BOOK_SIZE * EMBED_DIM);
    const float* c2b   = &g_c2[n * BOOK_SIZE];
    float4* ohz = (float4*)(out + CW_ELEMS + ((size_t)row0 * NUM_CODES + n) * BOOK_SIZE);
    const float4 zero4 = make_float4(0.f, 0.f, 0.f, 0.f);

    // Load x tile (transposed). 128 rows x 16 float4 columns, coalesced.
    for (int it = tid; it < MB * (EMBED_DIM / 4); it += 256) {
        int r  = it >> 4;
        int c4 = it & 15;
        float4 v = *(const float4*)(xbase + (size_t)r * (NUM_CODES * EMBED_DIM) + c4 * 4);
        xs[c4 * 4 + 0][r] = v.x;
        xs[c4 * 4 + 1][r] = v.y;
        xs[c4 * 4 + 2][r] = v.z;
        xs[c4 * 4 + 3][r] = v.w;
    }
    __syncthreads();

    // A fragments (bf16x2), one m16 row-set, K=64 = 4 k16-steps (16 regs).
    unsigned int a[4][4];
    #pragma unroll
    for (int s = 0; s < 4; s++) {
        int k0 = 16 * s + 2 * t;
        a[s][0] = pbf16(xs[k0    ][rw + g    ], xs[k0 + 1][rw + g    ]);
        a[s][1] = pbf16(xs[k0    ][rw + g + 8], xs[k0 + 1][rw + g + 8]);
        a[s][2] = pbf16(xs[k0 + 8][rw + g    ], xs[k0 + 9][rw + g    ]);
        a[s][3] = pbf16(xs[k0 + 8][rw + g + 8], xs[k0 + 9][rw + g + 8]);
    }

    // Per-thread top-3 packed keys for the 2 rows this thread owns.
    unsigned int kk[2][3];
    #pragma unroll
    for (int h = 0; h < 2; h++)
        #pragma unroll
        for (int j = 0; j < 3; j++) kk[h][j] = 0xFFFFFFFFu;

    unsigned int* csf32 = (unsigned int*)csf;
    int it2 = 0;   // zero-fill progress (1 float4/thread/tile-iter, 128 iters)

    for (int c0 = 0; c0 < BOOK_SIZE; c0 += CHUNK) {
        __syncthreads();
        // Fill csf: CHUNK codes x 16 float4 columns, pack to bf16x2 once.
        for (int it = tid; it < CHUNK * (EMBED_DIM / 4); it += 256) {
            int code = it >> 4;
            int c4   = it & 15;
            int s    = c4 >> 2;
            int p0   = (c4 & 3) * 2;
            float4 v = *(const float4*)(cbase + (size_t)(c0 + code) * EMBED_DIM + c4 * 4);
            unsigned int w0 = pbf16(v.x, v.y);
            unsigned int w1 = pbf16(v.z, v.w);
            int half = s >> 1, rem = (s & 1) * 2;
            int t0 = p0 & 3,        b0 = p0 >> 2;
            int t1 = (p0 + 1) & 3,  b1 = (p0 + 1) >> 2;
            csf32[(code * CSTR + t0 * 2 + half) * 4 + rem + b0] = w0;
            csf32[(code * CSTR + t1 * 2 + half) * 4 + rem + b1] = w1;
        }
        __syncthreads();

        #pragma unroll
        for (int tc = 0; tc < CHUNK / 8; tc++) {
            const int cbs = tc * 8;
            const int cg  = c0 + cbs;
            const int code = cbs + g;

            // background one-hot zero-fill: 1 coalesced float4 per thread
            {
                int L = it2 * 256 + tid;          // row = L>>8, f4 = L&255
                __stwt(&ohz[((size_t)(L >> 8)) * (NUM_CODES * 256) + (L & 255)], zero4);
                it2++;
            }

            // 2 LDS.128: full K=64 B fragment for this thread's code.
            uint4 U0 = csf[code * CSTR + t * 2    ];
            uint4 U1 = csf[code * CSTR + t * 2 + 1];

            float2 c2v = *(const float2*)(c2b + cg + 2 * t);   // biased c2
            unsigned int code0 = cg + 2 * t, code1 = code0 + 1;

            float d0 = 0.f, d1 = 0.f, d2 = 0.f, d3 = 0.f;
            mma_bf16(d0, d1, d2, d3, a[0][0], a[0][1], a[0][2], a[0][3], U0.x, U0.y);
            mma_bf16(d0, d1, d2, d3, a[1][0], a[1][1], a[1][2], a[1][3], U0.z, U0.w);
            mma_bf16(d0, d1, d2, d3, a[2][0], a[2][1], a[2][2], a[2][3], U1.x, U1.y);
            mma_bf16(d0, d1, d2, d3, a[3][0], a[3][1], a[3][2], a[3][3], U1.z, U1.w);

            unsigned int k;
            k = (__float_as_uint(fmaf(-2.0f, d0, c2v.x)) & 0xFFFFFC00u) | code0;
            ins3(kk[0][0], kk[0][1], kk[0][2], k);
            k = (__float_as_uint(fmaf(-2.0f, d1, c2v.y)) & 0xFFFFFC00u) | code1;
            ins3(kk[0][0], kk[0][1], kk[0][2], k);
            k = (__float_as_uint(fmaf(-2.0f, d2, c2v.x)) & 0xFFFFFC00u) | code0;
            ins3(kk[1][0], kk[1][1], kk[1][2], k);
            k = (__float_as_uint(fmaf(-2.0f, d3, c2v.y)) & 0xFFFFFC00u) | code1;
            ins3(kk[1][0], kk[1][1], kk[1][2], k);
        }
    }

    // Emit candidates: 4 quad-lanes x top-3 = 12 per row.
    #pragma unroll
    for (int h = 0; h < 2; h++) {
        int row  = row0 + rw + g + 8 * h;
        size_t base = (size_t)(row * NUM_CODES + n) * 12 + t * 3;
        #pragma unroll
        for (int j = 0; j < 3; j++) {
            g_cand[base + j] = (int)(kk[h][j] & 0x3FFu);
            g_cval[base + j] = __uint_as_float(kk[h][j] & 0xFFFFFC00u) - C2BIAS;
        }
    }
}

// ---------------------------------------------------------------------------
// Kernel 1.5: resolve each pair from its 12 candidates (warp-uniform
// branching; logic unchanged since R5/R10 — protected).
// ---------------------------------------------------------------------------
__global__ void __launch_bounds__(256)
refine_kernel(const float* __restrict__ x, const float* __restrict__ cb) {
    const int warp = threadIdx.x >> 5;
    const int lane = threadIdx.x & 31;
    const int pair = blockIdx.x * 8 + warp;
    if (pair >= NPAIR) return;

    int   cand = 0;
    float val  = 3.4e38f;
    if (lane < 12) {
        cand = g_cand[(size_t)pair * 12 + lane];
        val  = g_cval[(size_t)pair * 12 + lane];
    }

    float vmin = val;
    #pragma unroll
    for (int off = 16; off >= 1; off >>= 1)
        vmin = fminf(vmin, __shfl_xor_sync(0xffffffffu, vmin, off));

    bool active = (lane < 12) && (val <= vmin + MARGIN);
    unsigned actmask = __ballot_sync(0xffffffffu, active);
    int win;

    if (__popc(actmask) == 1) {
        int src = __ffs(actmask) - 1;
        win = __shfl_sync(0xffffffffu, cand, src);
    } else {
        const int b = pair >> 4;
        const int n = pair & 15;
        const float* xr = x + (size_t)b * (NUM_CODES * EMBED_DIM) + n * EMBED_DIM;

        double dj = 1e300;
        for (int j = 0; j < 12; j++) {
            if (!((actmask >> j) & 1u)) continue;
            int cidx = __shfl_sync(0xffffffffu, cand, j);
            const float* cc = cb + ((size_t)n * BOOK_SIZE + cidx) * EMBED_DIM;
            double d = 0.0;
            #pragma unroll
            for (int u = 0; u < 2; u++) {
                int k = lane + 32 * u;
                double xv = (double)xr[k];
                double cv = (double)cc[k];
                d += cv * cv - 2.0 * xv * cv;
            }
            #pragma unroll
            for (int off = 16; off >= 1; off >>= 1)
                d += __shfl_xor_sync(0xffffffffu, d, off);
            if (lane == j) dj = d;
        }

        double dmin = dj;
        #pragma unroll
        for (int off = 16; off >= 1; off >>= 1)
            dmin = fmin(dmin, __shfl_xor_sync(0xffffffffu, dmin, off));

        bool elig = ((actmask >> lane) & 1u) && (lane < 12) && (dj <= dmin + TIE_EPS);
        int key = elig ? cand : 0x7fffffff;
        #pragma unroll
        for (int off = 16; off >= 1; off >>= 1)
            key = min(key, __shfl_xor_sync(0xffffffffu, key, off));
        win = key;
    }

    if (lane == 0) g_idx[pair] = win;
}

// ---------------------------------------------------------------------------
// Kernel 2: finalize outputs. One warp per (b,n) pair.
// One-hot zeros already streamed by argmin_kernel.
// ---------------------------------------------------------------------------
__global__ void __launch_bounds__(256)
write_kernel(const float* __restrict__ cb, float* __restrict__ out) {
    const int warp = threadIdx.x >> 5;
    const int lane = threadIdx.x & 31;
    const int bn   = blockIdx.x * 8 + warp;
    const int b  = bn >> 4;
    const int n  = bn & 15;
    const int idx = g_idx[bn];

    if (lane == 0)
        out[CW_ELEMS + (size_t)bn * BOOK_SIZE + idx] = 1.0f;

    if (lane < 16) {
        float4 w = *(const float4*)(cb + ((size_t)n * BOOK_SIZE + idx) * EMBED_DIM + lane * 4);
        __stwt((float4*)(out + (size_t)b * (NUM_CODES * EMBED_DIM) + n * EMBED_DIM + lane * 4), w);
    }
}

// ---------------------------------------------------------------------------
extern "C" void kernel_launch(void* const* d_in, const int* in_sizes, int n_in,
                              void* d_out, int out_size) {
    const float* x  = (const float*)d_in[0];
    const float* cb = (const float*)d_in[1];
    if (n_in >= 2 && in_sizes[0] == NUM_CODES * BOOK_SIZE * EMBED_DIM) {
        const float* tmp = x; x = cb; cb = tmp;
    }
    float* out = (float*)d_out;

    c2_kernel<<<(NUM_CODES * BOOK_SIZE + 255) / 256, 256>>>(cb);

    dim3 g1(BATCH / MB, NUM_CODES);
    argmin_kernel<<<g1, 256>>>(x, cb, out);

    refine_kernel<<<NPAIR / 8, 256>>>(x, cb);

    write_kernel<<<NPAIR / 8, 256>>>(cb, out);
}

// round 15
// speedup vs baseline: 1.8227x; 1.0975x over previous
#include <cuda_runtime.h>
#include <cuda_bf16.h>

// Problem constants
#define BATCH     8192
#define NUM_CODES 16
#define BOOK_SIZE 1024
#define EMBED_DIM 64

// Tiling
#define MB     128   // x rows per CTA
#define CHUNK  64    // codebook rows per smem tile

#define NPAIR (BATCH * NUM_CODES)
#define CW_ELEMS ((size_t)BATCH * NUM_CODES * EMBED_DIM)   // 8,388,608

// Near-tie band on EXACT distance gap (proven in R5 pass — do not change)
#define TIE_EPS 4e-5
// refine gate: covers tf32 noise (~0.05 worst) + key truncation (<=0.0625)
#define MARGIN  0.35f
// bias making scores positive so uint order == float order
#define C2BIAS  512.0f

// B-fragment smem: 4 q-blocks of (CHUNK*4 + 1) uint4
#define QBLK (CHUNK * 4 + 1)

// Scratch (device globals; no allocation allowed)
__device__ float g_c2  [NUM_CODES * BOOK_SIZE];   // stores c2 + C2BIAS
__device__ int   g_cand[(size_t)NPAIR * 12];
__device__ float g_cval[(size_t)NPAIR * 12];

// ---------------------------------------------------------------------------
__device__ __forceinline__ unsigned int f2tf32(float f) {
    unsigned int r;
    asm("cvt.rna.tf32.f32 %0, %1;" : "=r"(r) : "f"(f));
    return r;
}
__device__ __forceinline__ void mma_tf32(float& d0, float& d1, float& d2, float& d3,
                                         unsigned int a0, unsigned int a1,
                                         unsigned int a2, unsigned int a3,
                                         unsigned int b0, unsigned int b1) {
    asm("mma.sync.aligned.m16n8k8.row.col.f32.tf32.tf32.f32 "
        "{%0,%1,%2,%3}, {%4,%5,%6,%7}, {%8,%9}, {%0,%1,%2,%3};"
        : "+f"(d0), "+f"(d1), "+f"(d2), "+f"(d3)
        : "r"(a0), "r"(a1), "r"(a2), "r"(a3), "r"(b0), "r"(b1));
}

// top-3 (ascending) insertion of key k into sorted triple: 5 integer min/max
__device__ __forceinline__ void ins3(unsigned int& k0, unsigned int& k1,
                                     unsigned int& k2, unsigned int k) {
    unsigned int a = umin(k, k0);
    unsigned int b = umax(k, k0);
    unsigned int c = umin(b, k1);
    unsigned int d = umax(b, k1);
    k2 = umin(d, k2);
    k1 = c;
    k0 = a;
}

// ---------------------------------------------------------------------------
// Kernel 0: codebook squared norms + bias.
// ---------------------------------------------------------------------------
__global__ void c2_kernel(const float* __restrict__ cb) {
    int code = blockIdx.x * blockDim.x + threadIdx.x;
    if (code < NUM_CODES * BOOK_SIZE) {
        const float4* p = (const float4*)(cb + (size_t)code * EMBED_DIM);
        float s = 0.f;
        #pragma unroll
        for (int i = 0; i < EMBED_DIM / 4; i++) {
            float4 v = p[i];
            s += v.x * v.x + v.y * v.y + v.z * v.z + v.w * v.w;
        }
        g_c2[code] = s + C2BIAS;
    }
}

// ---------------------------------------------------------------------------
// Kernel 1: tf32 tensor-core ranking + fused one-hot zero-fill (R10 champion,
// unchanged). 128 threads = 4 warps; warp w owns rows [w*32, w*32+32) as two
// m16 A-sets. Keys: (bits of (c2 + 512 - 2*dot) & ~0x3FF) | code.
// ---------------------------------------------------------------------------
__global__ void __launch_bounds__(128)
argmin_kernel(const float* __restrict__ x, const float* __restrict__ cb,
              float* __restrict__ out) {
    __shared__ float xs[EMBED_DIM][MB];        // 32 KB, transposed x tile
    __shared__ uint4 csf[4 * QBLK];            // ~16.4 KB, tf32 B fragments

    const int tid  = threadIdx.x;
    const int w    = tid >> 5;
    const int lane = tid & 31;
    const int g    = lane >> 2;
    const int t    = lane & 3;
    const int n    = blockIdx.y;
    const int row0 = blockIdx.x * MB;
    const int rw   = w * 32;   // warp's row base within tile (32 rows)

    const float* xbase = x  + (size_t)row0 * (NUM_CODES * EMBED_DIM) + n * EMBED_DIM;
    const float* cbase = cb + (size_t)n * (BOOK_SIZE * EMBED_DIM);
    const float* c2b   = &g_c2[n * BOOK_SIZE];
    float4* ohz = (float4*)(out + CW_ELEMS + ((size_t)row0 * NUM_CODES + n) * BOOK_SIZE);
    const float4 zero4 = make_float4(0.f, 0.f, 0.f, 0.f);

    // Load x tile (transposed). 128 rows x 16 float4 columns, coalesced.
    for (int it = tid; it < MB * (EMBED_DIM / 4); it += 128) {
        int r  = it >> 4;
        int c4 = it & 15;
        float4 v = *(const float4*)(xbase + (size_t)r * (NUM_CODES * EMBED_DIM) + c4 * 4);
        xs[c4 * 4 + 0][r] = v.x;
        xs[c4 * 4 + 1][r] = v.y;
        xs[c4 * 4 + 2][r] = v.z;
        xs[c4 * 4 + 3][r] = v.w;
    }
    __syncthreads();

    // A fragments, two m16 row-sets, full K=64 (8 k-steps), kept as tf32.
    unsigned int a[2][8][4];
    #pragma unroll
    for (int m = 0; m < 2; m++) {
        const int rb = rw + m * 16;
        #pragma unroll
        for (int s = 0; s < 8; s++) {
            a[m][s][0] = f2tf32(xs[8 * s + t    ][rb + g    ]);
            a[m][s][1] = f2tf32(xs[8 * s + t    ][rb + g + 8]);
            a[m][s][2] = f2tf32(xs[8 * s + t + 4][rb + g    ]);
            a[m][s][3] = f2tf32(xs[8 * s + t + 4][rb + g + 8]);
        }
    }

    // Per-thread top-3 packed keys for each of the 4 rows this thread owns.
    unsigned int kk[4][3];
    #pragma unroll
    for (int h = 0; h < 4; h++)
        #pragma unroll
        for (int j = 0; j < 3; j++) kk[h][j] = 0xFFFFFFFFu;

    unsigned int* csf32 = (unsigned int*)csf;
    int it2 = 0;   // zero-fill progress counter (2 float4 per tile iter)

    for (int c0 = 0; c0 < BOOK_SIZE; c0 += CHUNK) {
        __syncthreads();
        // Fill csf: CHUNK codes x 16 float4 columns; convert to tf32 once.
        for (int it = tid; it < CHUNK * (EMBED_DIM / 4); it += 128) {
            int code = it >> 4;
            int c4   = it & 15;
            int q    = c4 >> 2;
            int inr  = c4 & 3;
            float4 v = *(const float4*)(cbase + (size_t)(c0 + code) * EMBED_DIM + c4 * 4);
            unsigned int base = (q * QBLK + code * 4) * 4 + inr;
            csf32[base     ] = f2tf32(v.x);
            csf32[base + 4 ] = f2tf32(v.y);
            csf32[base + 8 ] = f2tf32(v.z);
            csf32[base + 12] = f2tf32(v.w);
        }
        __syncthreads();

        #pragma unroll
        for (int tc = 0; tc < CHUNK / 8; tc++) {
            const int cbs = tc * 8;
            const int cg  = c0 + cbs;
            const int code = cbs + g;

            // background one-hot zero-fill: 2 coalesced float4 per thread
            {
                int j0 = it2 * 2;
                int L0 = j0 * 128 + tid;          // row = L>>8, f4 = L&255
                int L1 = L0 + 128;
                __stwt(&ohz[((size_t)(L0 >> 8)) * (NUM_CODES * 256) + (L0 & 255)], zero4);
                __stwt(&ohz[((size_t)(L1 >> 8)) * (NUM_CODES * 256) + (L1 & 255)], zero4);
                it2++;
            }

            uint4 Q0 = csf[0 * QBLK + code * 4 + t];
            uint4 Q1 = csf[1 * QBLK + code * 4 + t];
            uint4 Q2 = csf[2 * QBLK + code * 4 + t];
            uint4 Q3 = csf[3 * QBLK + code * 4 + t];

            float2 c2v = *(const float2*)(c2b + cg + 2 * t);   // biased c2
            unsigned int code0 = cg + 2 * t, code1 = code0 + 1;

            #pragma unroll
            for (int m = 0; m < 2; m++) {
                float d0 = 0.f, d1 = 0.f, d2 = 0.f, d3 = 0.f;
                mma_tf32(d0, d1, d2, d3, a[m][0][0], a[m][0][1], a[m][0][2], a[m][0][3], Q0.x, Q0.y);
                mma_tf32(d0, d1, d2, d3, a[m][1][0], a[m][1][1], a[m][1][2], a[m][1][3], Q0.z, Q0.w);
                mma_tf32(d0, d1, d2, d3, a[m][2][0], a[m][2][1], a[m][2][2], a[m][2][3], Q1.x, Q1.y);
                mma_tf32(d0, d1, d2, d3, a[m][3][0], a[m][3][1], a[m][3][2], a[m][3][3], Q1.z, Q1.w);
                mma_tf32(d0, d1, d2, d3, a[m][4][0], a[m][4][1], a[m][4][2], a[m][4][3], Q2.x, Q2.y);
                mma_tf32(d0, d1, d2, d3, a[m][5][0], a[m][5][1], a[m][5][2], a[m][5][3], Q2.z, Q2.w);
                mma_tf32(d0, d1, d2, d3, a[m][6][0], a[m][6][1], a[m][6][2], a[m][6][3], Q3.x, Q3.y);
                mma_tf32(d0, d1, d2, d3, a[m][7][0], a[m][7][1], a[m][7][2], a[m][7][3], Q3.z, Q3.w);

                unsigned int k;
                k = (__float_as_uint(fmaf(-2.0f, d0, c2v.x)) & 0xFFFFFC00u) | code0;
                ins3(kk[2*m][0], kk[2*m][1], kk[2*m][2], k);
                k = (__float_as_uint(fmaf(-2.0f, d1, c2v.y)) & 0xFFFFFC00u) | code1;
                ins3(kk[2*m][0], kk[2*m][1], kk[2*m][2], k);
                k = (__float_as_uint(fmaf(-2.0f, d2, c2v.x)) & 0xFFFFFC00u) | code0;
                ins3(kk[2*m+1][0], kk[2*m+1][1], kk[2*m+1][2], k);
                k = (__float_as_uint(fmaf(-2.0f, d3, c2v.y)) & 0xFFFFFC00u) | code1;
                ins3(kk[2*m+1][0], kk[2*m+1][1], kk[2*m+1][2], k);
            }
        }
    }

    // Emit candidates: 4 quad-lanes x top-3 = 12 per row.
    #pragma unroll
    for (int h = 0; h < 4; h++) {
        int row  = row0 + rw + (h >> 1) * 16 + g + (h & 1) * 8;
        size_t base = (size_t)(row * NUM_CODES + n) * 12 + t * 3;
        #pragma unroll
        for (int j = 0; j < 3; j++) {
            g_cand[base + j] = (int)(kk[h][j] & 0x3FFu);
            g_cval[base + j] = __uint_as_float(kk[h][j] & 0xFFFFFC00u) - C2BIAS;
        }
    }
}

// ---------------------------------------------------------------------------
// Kernel 2 (merged refine + write): resolve each pair from its 12 candidates
// (decision rule bit-identical to the passing R5/R10 logic — protected), then
// write the hot 1.0f and gather the codeword. One warp per pair; `win` is
// warp-uniform in both paths.
// ---------------------------------------------------------------------------
__global__ void __launch_bounds__(256)
refine_write_kernel(const float* __restrict__ x, const float* __restrict__ cb,
                    float* __restrict__ out) {
    const int warp = threadIdx.x >> 5;
    const int lane = threadIdx.x & 31;
    const int pair = blockIdx.x * 8 + warp;
    if (pair >= NPAIR) return;

    const int b = pair >> 4;
    const int n = pair & 15;

    int   cand = 0;
    float val  = 3.4e38f;
    if (lane < 12) {
        cand = g_cand[(size_t)pair * 12 + lane];
        val  = g_cval[(size_t)pair * 12 + lane];
    }

    float vmin = val;
    #pragma unroll
    for (int off = 16; off >= 1; off >>= 1)
        vmin = fminf(vmin, __shfl_xor_sync(0xffffffffu, vmin, off));

    bool active = (lane < 12) && (val <= vmin + MARGIN);
    unsigned actmask = __ballot_sync(0xffffffffu, active);
    int win;

    if (__popc(actmask) == 1) {
        int src = __ffs(actmask) - 1;
        win = __shfl_sync(0xffffffffu, cand, src);
    } else {
        const float* xr = x + (size_t)b * (NUM_CODES * EMBED_DIM) + n * EMBED_DIM;

        double dj = 1e300;
        for (int j = 0; j < 12; j++) {
            if (!((actmask >> j) & 1u)) continue;
            int cidx = __shfl_sync(0xffffffffu, cand, j);
            const float* cc = cb + ((size_t)n * BOOK_SIZE + cidx) * EMBED_DIM;
            double d = 0.0;
            #pragma unroll
            for (int u = 0; u < 2; u++) {
                int k = lane + 32 * u;
                double xv = (double)xr[k];
                double cv = (double)cc[k];
                d += cv * cv - 2.0 * xv * cv;
            }
            #pragma unroll
            for (int off = 16; off >= 1; off >>= 1)
                d += __shfl_xor_sync(0xffffffffu, d, off);
            if (lane == j) dj = d;
        }

        double dmin = dj;
        #pragma unroll
        for (int off = 16; off >= 1; off >>= 1)
            dmin = fmin(dmin, __shfl_xor_sync(0xffffffffu, dmin, off));

        bool elig = ((actmask >> lane) & 1u) && (lane < 12) && (dj <= dmin + TIE_EPS);
        int key = elig ? cand : 0x7fffffff;
        #pragma unroll
        for (int off = 16; off >= 1; off >>= 1)
            key = min(key, __shfl_xor_sync(0xffffffffu, key, off));
        win = key;
    }

    // ---- output writes (win is warp-uniform) ----
    if (lane == 0)
        out[CW_ELEMS + (size_t)pair * BOOK_SIZE + win] = 1.0f;

    if (lane < 16) {
        float4 wv = *(const float4*)(cb + ((size_t)n * BOOK_SIZE + win) * EMBED_DIM + lane * 4);
        __stwt((float4*)(out + (size_t)b * (NUM_CODES * EMBED_DIM) + n * EMBED_DIM + lane * 4), wv);
    }
}

// ---------------------------------------------------------------------------
extern "C" void kernel_launch(void* const* d_in, const int* in_sizes, int n_in,
                              void* d_out, int out_size) {
    const float* x  = (const float*)d_in[0];
    const float* cb = (const float*)d_in[1];
    if (n_in >= 2 && in_sizes[0] == NUM_CODES * BOOK_SIZE * EMBED_DIM) {
        const float* tmp = x; x = cb; cb = tmp;
    }
    float* out = (float*)d_out;

    c2_kernel<<<(NUM_CODES * BOOK_SIZE + 255) / 256, 256>>>(cb);

    dim3 g1(BATCH / MB, NUM_CODES);
    argmin_kernel<<<g1, 128>>>(x, cb, out);

    refine_write_kernel<<<NPAIR / 8, 256>>>(x, cb, out);
}